// round 6
// baseline (speedup 1.0000x reference)
#include <cuda_runtime.h>

#define D 128
#define KN 32
#define MAXB 20000

__device__ float g_u[D];
__device__ float g_v[D];
__device__ float g_M[D * D];
__device__ float g_agg[MAXB * D];

// packed f32x2 FMA (Blackwell): acc = a*b + acc lanewise (exact fp32, 2 lanes)
#define FMA2(acc, a, b) \
    asm("fma.rn.f32x2 %0, %1, %2, %0;" : "+l"(acc) : "l"(a), "l"(b))

// ---------------------------------------------------------------------------
// Kernel P1: u/v precompute. 2 blocks x 128 threads.
// Warp w handles rows w*32 .. w*32+31 (4 warps x 32 = all 128 rows).
// ---------------------------------------------------------------------------
__global__ __launch_bounds__(128) void prep_uv(
    const float* __restrict__ kernel0,
    const float* __restrict__ kernel1,
    const float* __restrict__ aw) {
    int t    = threadIdx.x;
    int lane = t & 31;
    int w    = t >> 5;

    const float* mat = (blockIdx.x == 0) ? kernel1 : kernel0;
    const float* a   = aw + blockIdx.x * D;
    float*       out = (blockIdx.x == 0) ? g_u : g_v;

    float4 av = ((const float4*)a)[lane];
    const float4* m4 = (const float4*)mat;
#pragma unroll
    for (int j = 0; j < 32; ++j) {
        int r = w * 32 + j;
        float4 x = m4[r * 32 + lane];
        float s = x.x * av.x + x.y * av.y + x.z * av.z + x.w * av.w;
#pragma unroll
        for (int o = 16; o > 0; o >>= 1) s += __shfl_xor_sync(0xffffffffu, s, o);
        if (lane == 0) out[r] = s;
    }
}

// ---------------------------------------------------------------------------
// Kernel P2: M precompute. 128 blocks x 128 threads.
// ---------------------------------------------------------------------------
__global__ __launch_bounds__(128) void prep_M(
    const float* __restrict__ kernel1,
    const float* __restrict__ nw) {
    extern __shared__ float psm[];
    float* nws  = psm;          // D*D floats (64KB)
    float* krow = psm + D * D;  // D floats

    int b = blockIdx.x;
    int t = threadIdx.x;

    krow[t] = kernel1[b * D + t];
    const float4* nw4  = (const float4*)nw;
    float4*       nws4 = (float4*)nws;
#pragma unroll
    for (int it = 0; it < 32; ++it)
        nws4[it * 128 + t] = nw4[it * 128 + t];
    __syncthreads();

    float acc = 0.f;
#pragma unroll 16
    for (int j = 0; j < D; ++j)
        acc += krow[j] * nws[j * D + t];
    g_M[b * D + t] = acc;
}

// ---------------------------------------------------------------------------
// Kernel A: per-target attention (R1 structure — measured best). base offsets
// blockIdx so the kernel can be launched in two halves.
// ---------------------------------------------------------------------------
__global__ __launch_bounds__(128) void attn_kernel(
    const float* __restrict__ features,
    const int* __restrict__ node,
    const int* __restrict__ neigh,
    int base, int B) {
    __shared__ float nf[KN * D];   // 16 KB
    __shared__ float fnode[D];
    __shared__ float scores[KN];
    __shared__ float wts[KN];

    int b = base + blockIdx.x;
    if (b >= B) return;
    int tid  = threadIdx.x;
    int lane = tid & 31;
    int w    = tid >> 5;

    const float4* f4  = (const float4*)features;
    float4*       nf4 = (float4*)nf;

#pragma unroll
    for (int it = 0; it < 8; ++it) {
        int i  = it * 128 + tid;
        int k  = i >> 5;
        int c  = i & 31;
        int nb = __ldg(&neigh[b * KN + k]);
        nf4[i] = f4[(size_t)nb * 32 + c];
    }
    if (tid < 32) {
        int nd = __ldg(&node[b]);
        ((float4*)fnode)[tid] = f4[(size_t)nd * 32 + tid];
    }
    __syncthreads();

    float4 fv = ((const float4*)fnode)[lane];
    float4 vv = ((const float4*)g_v)[lane];
    float sn = fv.x * vv.x + fv.y * vv.y + fv.z * vv.z + fv.w * vv.w;
#pragma unroll
    for (int o = 16; o > 0; o >>= 1) sn += __shfl_xor_sync(0xffffffffu, sn, o);

    float4 uu = ((const float4*)g_u)[lane];
#pragma unroll
    for (int j = 0; j < 8; ++j) {
        int k = w * 8 + j;
        float4 x = nf4[k * 32 + lane];
        float s = x.x * uu.x + x.y * uu.y + x.z * uu.z + x.w * uu.w;
#pragma unroll
        for (int o = 16; o > 0; o >>= 1) s += __shfl_xor_sync(0xffffffffu, s, o);
        if (lane == 0) {
            float t = s + sn;
            scores[k] = (t > 0.f) ? t : 0.2f * t;
        }
    }
    __syncthreads();

    if (w == 0) {
        float sc = scores[lane];
        float m = sc;
#pragma unroll
        for (int o = 16; o > 0; o >>= 1) m = fmaxf(m, __shfl_xor_sync(0xffffffffu, m, o));
        float e = __expf(sc - m);
        float den = e;
#pragma unroll
        for (int o = 16; o > 0; o >>= 1) den += __shfl_xor_sync(0xffffffffu, den, o);
        wts[lane] = e / den;
    }
    __syncthreads();

    float acc = 0.f;
#pragma unroll
    for (int k = 0; k < KN; ++k) acc += wts[k] * nf[k * D + tid];
    g_agg[b * D + tid] = acc;
}

// ---------------------------------------------------------------------------
// Kernel G: out = agg @ M. 512 threads = 4 row-teams of 128 sharing one M
// stage (16 warps/SM). FMA2 inner loop (halved FFMA instruction count).
// Each team: 8-row register tile, aT transpose in its own smem slab.
// ---------------------------------------------------------------------------
__global__ __launch_bounds__(512) void out_gemm(float* __restrict__ out, int B) {
    extern __shared__ float sm[];
    float* Ms = sm;                      // D*D floats (64 KB)
    // 4 team slabs of D*8 floats each (16 KB total), layout [d*8 + r]
    int tid  = threadIdx.x;
    int team = tid >> 7;
    int t    = tid & 127;
    float* aT = sm + D * D + team * (D * 8);

    // stage M (512 threads, 8 float4 each)
    float4*       Ms4 = (float4*)Ms;
    const float4* gM4 = (const float4*)g_M;
#pragma unroll
    for (int it = 0; it < 8; ++it) Ms4[it * 512 + tid] = gM4[it * 512 + tid];

    int ngroups = (B + 31) >> 5;         // 32 rows per block-iteration
    for (int g = blockIdx.x; g < ngroups; g += gridDim.x) {
        int r0 = (g << 5) + team * 8;

        float v[8];
#pragma unroll
        for (int r = 0; r < 8; ++r) {
            int row = r0 + r;
            v[r] = (row < B) ? g_agg[row * D + t] : 0.f;
        }
        __syncthreads();
        ((float4*)aT)[t * 2]     = make_float4(v[0], v[1], v[2], v[3]);
        ((float4*)aT)[t * 2 + 1] = make_float4(v[4], v[5], v[6], v[7]);
        __syncthreads();

        unsigned long long acc01 = 0ull, acc23 = 0ull, acc45 = 0ull, acc67 = 0ull;
#pragma unroll 16
        for (int d = 0; d < D; ++d) {
            float m = Ms[d * D + t];
            unsigned long long mm;
            asm("mov.b64 %0, {%1, %1};" : "=l"(mm) : "f"(m));
            ulonglong2 p0 = *((const ulonglong2*)(aT + d * 8));
            ulonglong2 p1 = *((const ulonglong2*)(aT + d * 8 + 4));
            FMA2(acc01, p0.x, mm);
            FMA2(acc23, p0.y, mm);
            FMA2(acc45, p1.x, mm);
            FMA2(acc67, p1.y, mm);
        }

        float r_[8];
        asm("mov.b64 {%0, %1}, %2;" : "=f"(r_[0]), "=f"(r_[1]) : "l"(acc01));
        asm("mov.b64 {%0, %1}, %2;" : "=f"(r_[2]), "=f"(r_[3]) : "l"(acc23));
        asm("mov.b64 {%0, %1}, %2;" : "=f"(r_[4]), "=f"(r_[5]) : "l"(acc45));
        asm("mov.b64 {%0, %1}, %2;" : "=f"(r_[6]), "=f"(r_[7]) : "l"(acc67));
#pragma unroll
        for (int r = 0; r < 8; ++r) {
            int row = r0 + r;
            if (row < B) out[row * D + t] = r_[r];
        }
    }
}

// ---------------------------------------------------------------------------
extern "C" void kernel_launch(void* const* d_in, const int* in_sizes, int n_in,
                              void* d_out, int out_size) {
    const float* features = (const float*)d_in[0];
    const int*   node     = (const int*)d_in[1];
    const int*   neigh    = (const int*)d_in[2];
    const float* kern0    = (const float*)d_in[3];
    const float* kern1    = (const float*)d_in[4];
    const float* aw       = (const float*)d_in[5];
    const float* nw       = (const float*)d_in[6];
    float*       out      = (float*)d_out;

    int B = in_sizes[1];
    if (B > MAXB) B = MAXB;
    int half = (B + 1) / 2;

    prep_uv<<<2, D>>>(kern0, kern1, aw);

    // attn in two halves (no perf cost; shifts ncu capture slot onto attn)
    attn_kernel<<<half, D>>>(features, node, neigh, 0, B);
    attn_kernel<<<B - half, D>>>(features, node, neigh, half, B);

    const int prepM_smem = (D * D + D) * sizeof(float);           // ~66 KB
    cudaFuncSetAttribute(prep_M, cudaFuncAttributeMaxDynamicSharedMemorySize, prepM_smem);
    prep_M<<<D, D, prepM_smem>>>(kern1, nw);

    const int gemm_smem = (D * D + 4 * D * 8) * sizeof(float);    // 80 KB
    cudaFuncSetAttribute(out_gemm, cudaFuncAttributeMaxDynamicSharedMemorySize, gemm_smem);
    out_gemm<<<296, 512, gemm_smem>>>(out, B);
}

// round 7
// speedup vs baseline: 1.0309x; 1.0309x over previous
#include <cuda_runtime.h>

#define D 128
#define KN 32
#define MAXB 20000

__device__ float g_u[D];
__device__ float g_v[D];
__device__ float g_M[D * D];
__device__ float g_agg[MAXB * D];

// ---------------------------------------------------------------------------
// Kernel P1: u or v precompute. 1 block x 128 threads per launch.
// which=0: u[d] = dot(kernel1[d,:], aw[0:D]); which=1: v from kernel0/aw[D:].
// Warp w handles rows w*32 .. w*32+31.
// ---------------------------------------------------------------------------
__global__ __launch_bounds__(128) void prep_uv(
    const float* __restrict__ kernel0,
    const float* __restrict__ kernel1,
    const float* __restrict__ aw,
    int which) {
    int t    = threadIdx.x;
    int lane = t & 31;
    int w    = t >> 5;

    const float* mat = (which == 0) ? kernel1 : kernel0;
    const float* a   = aw + which * D;
    float*       out = (which == 0) ? g_u : g_v;

    float4 av = ((const float4*)a)[lane];
    const float4* m4 = (const float4*)mat;
#pragma unroll
    for (int j = 0; j < 32; ++j) {
        int r = w * 32 + j;
        float4 x = m4[r * 32 + lane];
        float s = x.x * av.x + x.y * av.y + x.z * av.z + x.w * av.w;
#pragma unroll
        for (int o = 16; o > 0; o >>= 1) s += __shfl_xor_sync(0xffffffffu, s, o);
        if (lane == 0) out[r] = s;
    }
}

// ---------------------------------------------------------------------------
// Kernel P2: M precompute. 128 blocks x 128 threads (measured ~8.5us).
// ---------------------------------------------------------------------------
__global__ __launch_bounds__(128) void prep_M(
    const float* __restrict__ kernel1,
    const float* __restrict__ nw) {
    extern __shared__ float psm[];
    float* nws  = psm;          // D*D floats (64KB)
    float* krow = psm + D * D;  // D floats

    int b = blockIdx.x;
    int t = threadIdx.x;

    krow[t] = kernel1[b * D + t];
    const float4* nw4  = (const float4*)nw;
    float4*       nws4 = (float4*)nws;
#pragma unroll
    for (int it = 0; it < 32; ++it)
        nws4[it * 128 + t] = nw4[it * 128 + t];
    __syncthreads();

    float acc = 0.f;
#pragma unroll 16
    for (int j = 0; j < D; ++j)
        acc += krow[j] * nws[j * D + t];
    g_M[b * D + t] = acc;
}

// ---------------------------------------------------------------------------
// Kernel A: per-target attention (R1/R5 structure — measured best). Single
// launch, grid = B. Launched 4th so ncu captures it.
// ---------------------------------------------------------------------------
__global__ __launch_bounds__(128) void attn_kernel(
    const float* __restrict__ features,
    const int* __restrict__ node,
    const int* __restrict__ neigh,
    int B) {
    __shared__ float nf[KN * D];   // 16 KB
    __shared__ float fnode[D];
    __shared__ float scores[KN];
    __shared__ float wts[KN];

    int b = blockIdx.x;
    if (b >= B) return;
    int tid  = threadIdx.x;
    int lane = tid & 31;
    int w    = tid >> 5;

    const float4* f4  = (const float4*)features;
    float4*       nf4 = (float4*)nf;

#pragma unroll
    for (int it = 0; it < 8; ++it) {
        int i  = it * 128 + tid;
        int k  = i >> 5;
        int c  = i & 31;
        int nb = __ldg(&neigh[b * KN + k]);
        nf4[i] = f4[(size_t)nb * 32 + c];
    }
    if (tid < 32) {
        int nd = __ldg(&node[b]);
        ((float4*)fnode)[tid] = f4[(size_t)nd * 32 + tid];
    }
    __syncthreads();

    float4 fv = ((const float4*)fnode)[lane];
    float4 vv = ((const float4*)g_v)[lane];
    float sn = fv.x * vv.x + fv.y * vv.y + fv.z * vv.z + fv.w * vv.w;
#pragma unroll
    for (int o = 16; o > 0; o >>= 1) sn += __shfl_xor_sync(0xffffffffu, sn, o);

    float4 uu = ((const float4*)g_u)[lane];
#pragma unroll
    for (int j = 0; j < 8; ++j) {
        int k = w * 8 + j;
        float4 x = nf4[k * 32 + lane];
        float s = x.x * uu.x + x.y * uu.y + x.z * uu.z + x.w * uu.w;
#pragma unroll
        for (int o = 16; o > 0; o >>= 1) s += __shfl_xor_sync(0xffffffffu, s, o);
        if (lane == 0) {
            float t = s + sn;
            scores[k] = (t > 0.f) ? t : 0.2f * t;
        }
    }
    __syncthreads();

    if (w == 0) {
        float sc = scores[lane];
        float m = sc;
#pragma unroll
        for (int o = 16; o > 0; o >>= 1) m = fmaxf(m, __shfl_xor_sync(0xffffffffu, m, o));
        float e = __expf(sc - m);
        float den = e;
#pragma unroll
        for (int o = 16; o > 0; o >>= 1) den += __shfl_xor_sync(0xffffffffu, den, o);
        wts[lane] = e / den;
    }
    __syncthreads();

    float acc = 0.f;
#pragma unroll
    for (int k = 0; k < KN; ++k) acc += wts[k] * nf[k * D + tid];
    g_agg[b * D + tid] = acc;
}

// ---------------------------------------------------------------------------
// Kernel G: out = agg @ M. 256 threads = 2 row-teams of 128 sharing one M
// stage (72 KB smem -> 3 blocks/SM = 24 warps/SM, double R5's residency).
// float4 inner loop (R5-measured structure).
// ---------------------------------------------------------------------------
__global__ __launch_bounds__(256) void out_gemm(float* __restrict__ out, int B) {
    extern __shared__ float sm[];
    float* Ms = sm;                      // D*D floats (64 KB)
    int tid  = threadIdx.x;
    int team = tid >> 7;
    int t    = tid & 127;
    float* aT = sm + D * D + team * (D * 8);   // per-team 4 KB slab

    // stage M (256 threads, 16 float4 each)
    float4*       Ms4 = (float4*)Ms;
    const float4* gM4 = (const float4*)g_M;
#pragma unroll
    for (int it = 0; it < 16; ++it) Ms4[it * 256 + tid] = gM4[it * 256 + tid];

    int ngroups = (B + 15) >> 4;         // 16 rows per block-iteration
    for (int g = blockIdx.x; g < ngroups; g += gridDim.x) {
        int r0 = (g << 4) + team * 8;

        float v[8];
#pragma unroll
        for (int r = 0; r < 8; ++r) {
            int row = r0 + r;
            v[r] = (row < B) ? g_agg[row * D + t] : 0.f;
        }
        __syncthreads();
        ((float4*)aT)[t * 2]     = make_float4(v[0], v[1], v[2], v[3]);
        ((float4*)aT)[t * 2 + 1] = make_float4(v[4], v[5], v[6], v[7]);
        __syncthreads();

        float acc[8] = {0.f, 0.f, 0.f, 0.f, 0.f, 0.f, 0.f, 0.f};
#pragma unroll 16
        for (int d = 0; d < D; ++d) {
            float m = Ms[d * D + t];
            float4 a0 = ((const float4*)aT)[d * 2];
            float4 a1 = ((const float4*)aT)[d * 2 + 1];
            acc[0] += a0.x * m; acc[1] += a0.y * m;
            acc[2] += a0.z * m; acc[3] += a0.w * m;
            acc[4] += a1.x * m; acc[5] += a1.y * m;
            acc[6] += a1.z * m; acc[7] += a1.w * m;
        }
#pragma unroll
        for (int r = 0; r < 8; ++r) {
            int row = r0 + r;
            if (row < B) out[row * D + t] = acc[r];
        }
    }
}

// ---------------------------------------------------------------------------
extern "C" void kernel_launch(void* const* d_in, const int* in_sizes, int n_in,
                              void* d_out, int out_size) {
    const float* features = (const float*)d_in[0];
    const int*   node     = (const int*)d_in[1];
    const int*   neigh    = (const int*)d_in[2];
    const float* kern0    = (const float*)d_in[3];
    const float* kern1    = (const float*)d_in[4];
    const float* aw       = (const float*)d_in[5];
    const float* nw       = (const float*)d_in[6];
    float*       out      = (float*)d_out;

    int B = in_sizes[1];
    if (B > MAXB) B = MAXB;

    // Launch order chosen so attn is the 4th launch (ncu capture slot).
    // Stream serialization makes ordering time-neutral; deps still flow.
    prep_uv<<<1, D>>>(kern0, kern1, aw, 0);   // 1: u
    prep_uv<<<1, D>>>(kern0, kern1, aw, 1);   // 2: v

    const int prepM_smem = (D * D + D) * sizeof(float);           // ~66 KB
    cudaFuncSetAttribute(prep_M, cudaFuncAttributeMaxDynamicSharedMemorySize, prepM_smem);
    prep_M<<<D, D, prepM_smem>>>(kern1, nw);  // 3: M

    attn_kernel<<<B, D>>>(features, node, neigh, B);  // 4: attn (profiled)

    const int gemm_smem = (D * D + 2 * D * 8) * sizeof(float);    // 72 KB
    cudaFuncSetAttribute(out_gemm, cudaFuncAttributeMaxDynamicSharedMemorySize, gemm_smem);
    out_gemm<<<444, 256, gemm_smem>>>(out, B);        // 5: gemm
}

// round 8
// speedup vs baseline: 1.2901x; 1.2515x over previous
#include <cuda_runtime.h>

#define D 128
#define KN 32
#define MAXB 20000

__device__ float g_u[D];
__device__ float g_v[D];
__device__ float g_M[D * D];
__device__ float g_agg[MAXB * D];

// ---------------------------------------------------------------------------
// Kernel P1: u or v precompute. 1 block x 128 threads per launch.
// which=0: u[d] = dot(kernel1[d,:], aw[0:D]); which=1: v from kernel0/aw[D:].
// ---------------------------------------------------------------------------
__global__ __launch_bounds__(128) void prep_uv(
    const float* __restrict__ kernel0,
    const float* __restrict__ kernel1,
    const float* __restrict__ aw,
    int which) {
    int t    = threadIdx.x;
    int lane = t & 31;
    int w    = t >> 5;

    const float* mat = (which == 0) ? kernel1 : kernel0;
    const float* a   = aw + which * D;
    float*       out = (which == 0) ? g_u : g_v;

    float4 av = ((const float4*)a)[lane];
    const float4* m4 = (const float4*)mat;
#pragma unroll
    for (int j = 0; j < 32; ++j) {
        int r = w * 32 + j;
        float4 x = m4[r * 32 + lane];
        float s = x.x * av.x + x.y * av.y + x.z * av.z + x.w * av.w;
#pragma unroll
        for (int o = 16; o > 0; o >>= 1) s += __shfl_xor_sync(0xffffffffu, s, o);
        if (lane == 0) out[r] = s;
    }
}

// ---------------------------------------------------------------------------
// Kernel P2: M precompute. 128 blocks x 128 threads (measured ~8.5us).
// ---------------------------------------------------------------------------
__global__ __launch_bounds__(128) void prep_M(
    const float* __restrict__ kernel1,
    const float* __restrict__ nw) {
    extern __shared__ float psm[];
    float* nws  = psm;          // D*D floats (64KB)
    float* krow = psm + D * D;  // D floats

    int b = blockIdx.x;
    int t = threadIdx.x;

    krow[t] = kernel1[b * D + t];
    const float4* nw4  = (const float4*)nw;
    float4*       nws4 = (float4*)nws;
#pragma unroll
    for (int it = 0; it < 32; ++it)
        nws4[it * 128 + t] = nw4[it * 128 + t];
    __syncthreads();

    float acc = 0.f;
#pragma unroll 16
    for (int j = 0; j < D; ++j)
        acc += krow[j] * nws[j * D + t];
    g_M[b * D + t] = acc;
}

// ---------------------------------------------------------------------------
// Kernel A: per-target attention — register-resident rows (no nf smem).
// Warp w, iteration it holds row (it*4+w) entirely across its 32 lanes.
// Scores + weighted aggregate computed from those registers; only a 2KB
// cross-warp partial reduction goes through smem.
// ---------------------------------------------------------------------------
__global__ __launch_bounds__(128) void attn_kernel(
    const float* __restrict__ features,
    const int* __restrict__ node,
    const int* __restrict__ neigh,
    int B) {
    __shared__ float scores[KN];
    __shared__ float wts[KN];
    __shared__ float part[4 * D];   // per-warp partial sums (2 KB)

    int b = blockIdx.x;
    if (b >= B) return;
    int tid  = threadIdx.x;
    int lane = tid & 31;
    int w    = tid >> 5;

    const float4* f4 = (const float4*)features;

    // gather 8 rows per warp into registers: row r(it) = it*4 + w
    float4 x[8];
#pragma unroll
    for (int it = 0; it < 8; ++it) {
        int k  = it * 4 + w;
        int nb = __ldg(&neigh[b * KN + k]);
        x[it]  = f4[(size_t)nb * 32 + lane];
    }

    // sn = dot(node_row, v): per-warp redundant, registers only
    int nd = __ldg(&node[b]);
    float4 fv = f4[(size_t)nd * 32 + lane];
    float4 vv = ((const float4*)g_v)[lane];
    float sn = fv.x * vv.x + fv.y * vv.y + fv.z * vv.z + fv.w * vv.w;
#pragma unroll
    for (int o = 16; o > 0; o >>= 1) sn += __shfl_xor_sync(0xffffffffu, sn, o);

    // scores from registers: s(it) = dot(row, u)
    float4 uu = ((const float4*)g_u)[lane];
#pragma unroll
    for (int it = 0; it < 8; ++it) {
        float s = x[it].x * uu.x + x[it].y * uu.y + x[it].z * uu.z + x[it].w * uu.w;
#pragma unroll
        for (int o = 16; o > 0; o >>= 1) s += __shfl_xor_sync(0xffffffffu, s, o);
        if (lane == 0) {
            float t = s + sn;
            scores[it * 4 + w] = (t > 0.f) ? t : 0.2f * t;   // leaky_relu
        }
    }
    __syncthreads();

    // softmax over K=32 (warp 0)
    if (w == 0) {
        float sc = scores[lane];
        float m = sc;
#pragma unroll
        for (int o = 16; o > 0; o >>= 1) m = fmaxf(m, __shfl_xor_sync(0xffffffffu, m, o));
        float e = __expf(sc - m);
        float den = e;
#pragma unroll
        for (int o = 16; o > 0; o >>= 1) den += __shfl_xor_sync(0xffffffffu, den, o);
        wts[lane] = e / den;
    }
    __syncthreads();

    // weighted aggregate from registers: per-warp partial over its 8 rows
    float4 p = make_float4(0.f, 0.f, 0.f, 0.f);
#pragma unroll
    for (int it = 0; it < 8; ++it) {
        float wk = wts[it * 4 + w];
        p.x += wk * x[it].x;
        p.y += wk * x[it].y;
        p.z += wk * x[it].z;
        p.w += wk * x[it].w;
    }
    ((float4*)part)[w * 32 + lane] = p;
    __syncthreads();

    // cross-warp reduce: thread tid sums column tid over 4 warps
    float acc = part[tid] + part[D + tid] + part[2 * D + tid] + part[3 * D + tid];
    g_agg[b * D + tid] = acc;
}

// ---------------------------------------------------------------------------
// Kernel G: out = agg @ M (exact R5-measured form: 128 threads, float4).
// ---------------------------------------------------------------------------
__global__ __launch_bounds__(128) void out_gemm(float* __restrict__ out, int B) {
    extern __shared__ float sm[];
    float* Ms = sm;            // D*D floats (64 KB)
    float* aT = sm + D * D;    // D*8 floats (4 KB), layout [d*8 + r]

    int tid = threadIdx.x;

    float4*       Ms4 = (float4*)Ms;
    const float4* gM4 = (const float4*)g_M;
#pragma unroll
    for (int it = 0; it < 32; ++it) Ms4[it * 128 + tid] = gM4[it * 128 + tid];

    int ngroups = (B + 7) >> 3;
    for (int g = blockIdx.x; g < ngroups; g += gridDim.x) {
        int r0 = g << 3;

        float v[8];
#pragma unroll
        for (int r = 0; r < 8; ++r) {
            int row = r0 + r;
            v[r] = (row < B) ? g_agg[row * D + tid] : 0.f;
        }
        __syncthreads();
        ((float4*)aT)[tid * 2]     = make_float4(v[0], v[1], v[2], v[3]);
        ((float4*)aT)[tid * 2 + 1] = make_float4(v[4], v[5], v[6], v[7]);
        __syncthreads();

        float acc[8] = {0.f, 0.f, 0.f, 0.f, 0.f, 0.f, 0.f, 0.f};
#pragma unroll 16
        for (int d = 0; d < D; ++d) {
            float m = Ms[d * D + tid];
            float4 a0 = ((const float4*)aT)[d * 2];
            float4 a1 = ((const float4*)aT)[d * 2 + 1];
            acc[0] += a0.x * m; acc[1] += a0.y * m;
            acc[2] += a0.z * m; acc[3] += a0.w * m;
            acc[4] += a1.x * m; acc[5] += a1.y * m;
            acc[6] += a1.z * m; acc[7] += a1.w * m;
        }
#pragma unroll
        for (int r = 0; r < 8; ++r) {
            int row = r0 + r;
            if (row < B) out[row * D + tid] = acc[r];
        }
    }
}

// ---------------------------------------------------------------------------
extern "C" void kernel_launch(void* const* d_in, const int* in_sizes, int n_in,
                              void* d_out, int out_size) {
    const float* features = (const float*)d_in[0];
    const int*   node     = (const int*)d_in[1];
    const int*   neigh    = (const int*)d_in[2];
    const float* kern0    = (const float*)d_in[3];
    const float* kern1    = (const float*)d_in[4];
    const float* aw       = (const float*)d_in[5];
    const float* nw       = (const float*)d_in[6];
    float*       out      = (float*)d_out;

    int B = in_sizes[1];
    if (B > MAXB) B = MAXB;

    // attn stays the 4th launch (ncu capture slot).
    prep_uv<<<1, D>>>(kern0, kern1, aw, 0);   // 1: u
    prep_uv<<<1, D>>>(kern0, kern1, aw, 1);   // 2: v

    const int prepM_smem = (D * D + D) * sizeof(float);        // ~66 KB
    cudaFuncSetAttribute(prep_M, cudaFuncAttributeMaxDynamicSharedMemorySize, prepM_smem);
    prep_M<<<D, D, prepM_smem>>>(kern1, nw);  // 3: M

    attn_kernel<<<B, D>>>(features, node, neigh, B);  // 4: attn (profiled)

    const int gemm_smem = (D * D + D * 8) * sizeof(float);     // 68 KB
    cudaFuncSetAttribute(out_gemm, cudaFuncAttributeMaxDynamicSharedMemorySize, gemm_smem);
    out_gemm<<<444, D, gemm_smem>>>(out, B);          // 5: gemm
}